// round 11
// baseline (speedup 1.0000x reference)
#include <cuda_runtime.h>
#include <cuda_fp16.h>
#include <math.h>

#define BATCH 4
#define CC    256
#define CQ    32
#define NTOK  4096
#define LOG2E 1.4426950408889634f

__device__ __half g_qh[BATCH * NTOK * CQ];   // q * log2e, fp16 hi
__device__ __half g_ql[BATCH * NTOK * CQ];   // fp16 lo
__device__ __half g_kh[BATCH * NTOK * CQ];
__device__ __half g_kl[BATCH * NTOK * CQ];
__device__ __half g_vh[BATCH * CC * NTOK];   // [b][o][n] fp16

__device__ __forceinline__ void mma16(float4& d, const unsigned* a, unsigned b0, unsigned b1) {
    asm volatile(
        "mma.sync.aligned.m16n8k16.row.col.f32.f16.f16.f32 "
        "{%0,%1,%2,%3},{%4,%5,%6,%7},{%8,%9},{%0,%1,%2,%3};"
        : "+f"(d.x), "+f"(d.y), "+f"(d.z), "+f"(d.w)
        : "r"(a[0]), "r"(a[1]), "r"(a[2]), "r"(a[3]), "r"(b0), "r"(b1));
}
__device__ __forceinline__ void cpa16(unsigned dst, const void* src) {
    asm volatile("cp.async.ca.shared.global [%0], [%1], 16;" :: "r"(dst), "l"(src));
}
__device__ __forceinline__ float ex2(float x) {
    float r; asm("ex2.approx.f32 %0, %1;" : "=f"(r) : "f"(x)); return r;
}

// ============ Kernel 1: projections + fp16 layout production ============
__global__ __launch_bounds__(256) void proj_kernel(
    const float* __restrict__ x,
    const float* __restrict__ wq, const float* __restrict__ bq,
    const float* __restrict__ wk, const float* __restrict__ bk,
    const float* __restrict__ wv, const float* __restrict__ bv)
{
    __shared__ float sX[32 * 128];
    __shared__ float sW[32 * 68];
    const int n0 = blockIdx.x * 128, r0 = blockIdx.y * 64, b = blockIdx.z;
    const int t = threadIdx.x, rg = t >> 4, ng = t & 15;
    float acc[4][8];
#pragma unroll
    for (int j = 0; j < 4; j++)
#pragma unroll
        for (int i = 0; i < 8; i++) acc[j][i] = 0.0f;
    for (int cc = 0; cc < CC; cc += 32) {
#pragma unroll
        for (int p = 0; p < 4; p++) {
            int idx = p * 256 + t, cr = idx >> 5, l = idx & 31;
            float4 v = *(const float4*)(x + ((size_t)b * CC + cc + cr) * NTOK + n0 + 4 * l);
            *(float4*)(sX + cr * 128 + 4 * l) = v;
        }
#pragma unroll
        for (int p = 0; p < 2; p++) {
            int idx = p * 256 + t, rl = idx >> 3, cf = idx & 7;
            int rglob = r0 + rl;
            const float* wrow;
            if (rglob < CQ)          wrow = wq + (size_t)rglob * CC;
            else if (rglob < 2 * CQ) wrow = wk + (size_t)(rglob - CQ) * CC;
            else                     wrow = wv + (size_t)(rglob - 2 * CQ) * CC;
            float4 v = *(const float4*)(wrow + cc + 4 * cf);
            sW[(4 * cf + 0) * 68 + rl] = v.x;
            sW[(4 * cf + 1) * 68 + rl] = v.y;
            sW[(4 * cf + 2) * 68 + rl] = v.z;
            sW[(4 * cf + 3) * 68 + rl] = v.w;
        }
        __syncthreads();
#pragma unroll
        for (int c = 0; c < 32; c++) {
            float4 w  = *(float4*)(sW + c * 68 + 4 * rg);
            float4 x1 = *(float4*)(sX + c * 128 + 4 * ng);
            float4 x2 = *(float4*)(sX + c * 128 + 64 + 4 * ng);
            float wj[4] = {w.x, w.y, w.z, w.w};
            float xs[8] = {x1.x, x1.y, x1.z, x1.w, x2.x, x2.y, x2.z, x2.w};
#pragma unroll
            for (int j = 0; j < 4; j++)
#pragma unroll
                for (int i = 0; i < 8; i++) acc[j][i] = fmaf(wj[j], xs[i], acc[j][i]);
        }
        __syncthreads();
    }
#pragma unroll
    for (int j = 0; j < 4; j++) {
        int rglob = r0 + 4 * rg + j;
        if (rglob < 2 * CQ) {
            bool isq = rglob < CQ;
            int c = isq ? rglob : rglob - CQ;
            float bias = isq ? bq[c] : bk[c];
            float scale = isq ? LOG2E : 1.0f;
            __half* dh = (isq ? g_qh : g_kh) + (size_t)b * NTOK * CQ + c;
            __half* dl = (isq ? g_ql : g_kl) + (size_t)b * NTOK * CQ + c;
#pragma unroll
            for (int i = 0; i < 8; i++) {
                int n = (i < 4) ? (n0 + 4 * ng + i) : (n0 + 64 + 4 * ng + i - 4);
                float v = (acc[j][i] + bias) * scale;
                __half h = __float2half_rn(v);
                dh[(size_t)n * CQ] = h;
                dl[(size_t)n * CQ] = __float2half_rn(v - __half2float(h));
            }
        } else {
            int o = rglob - 2 * CQ;
            float bias = bv[o];
            __half* dst = g_vh + ((size_t)b * CC + o) * NTOK;
            __half2 h0 = __floats2half2_rn(acc[j][0] + bias, acc[j][1] + bias);
            __half2 h1 = __floats2half2_rn(acc[j][2] + bias, acc[j][3] + bias);
            __half2 h2 = __floats2half2_rn(acc[j][4] + bias, acc[j][5] + bias);
            __half2 h3 = __floats2half2_rn(acc[j][6] + bias, acc[j][7] + bias);
            *(__half2*)(dst + n0 + 4 * ng)          = h0;
            *(__half2*)(dst + n0 + 4 * ng + 2)      = h1;
            *(__half2*)(dst + n0 + 64 + 4 * ng)     = h2;
            *(__half2*)(dst + n0 + 64 + 4 * ng + 2) = h3;
        }
    }
}

// ============ Kernel 2: flash attention, balanced online softmax ============
#define OQH  0
#define OQL  1280
#define OKH0 2560
#define OKL0 3200
#define OKH1 3840
#define OKL1 4480
#define OV0  5120
#define OV1  10240
#define OP   15360
#define OSUM 16640
#define OLM  16768
#define SMEM_WORDS 16896

__global__ __launch_bounds__(256, 2) void attn_kernel(
    const float* __restrict__ x,
    const float* __restrict__ gamma,
    float* __restrict__ out)
{
    extern __shared__ unsigned su[];
    unsigned* uP = su + OP;
    float* sSum = (float*)(su + OSUM);
    float* sLm  = (float*)(su + OLM);

    const int t = threadIdx.x, w = t >> 5, lane = t & 31;
    const int quad = lane & 3, qr = lane >> 2;
    const int w_rg = w >> 1, w_h = w & 1;            // S: rows 16*w_rg, cols 16*w_h
    const int m_base = 32 * (w >> 2), o_base = 64 * (w & 3);  // PV map
    const int b = blockIdx.x >> 6, q0 = (blockIdx.x & 63) * 64;
    const unsigned sbase = (unsigned)__cvta_generic_to_shared(su);

    const __half* khp = g_kh + (size_t)b * NTOK * CQ;
    const __half* klp = g_kl + (size_t)b * NTOK * CQ;
    const __half* vb  = g_vh + (size_t)b * CC * NTOK;

    // ---- Q staging (once) ----
    {
        int r = t >> 2, qw = t & 3;
        size_t off = ((size_t)b * NTOK + q0 + r) * CQ + qw * 8;
        *(uint4*)(su + OQH + r * 20 + qw * 4) = *(const uint4*)(g_qh + off);
        *(uint4*)(su + OQL + r * 20 + qw * 4) = *(const uint4*)(g_ql + off);
    }

    // ---- cp.async source/dest precompute ----
    const int vc = t & 3, vrow = t >> 2;
    const __half* vsrc = vb + (size_t)vrow * NTOK + vc * 8;
    const int krow = (t >> 2) & 31, kc = t & 3;
    const __half* ksrc = ((t < 128) ? khp : klp) + (size_t)krow * CQ + kc * 8;
    const unsigned koff0 = ((t < 128) ? OKH0 : OKL0) + krow * 20 + kc * 4;
    const unsigned koff1 = ((t < 128) ? OKH1 : OKL1) + krow * 20 + kc * 4;

    // prologue: tile 0 -> buffer 0
    {
#pragma unroll
        for (int r = 0; r < 4; r++)
            cpa16(sbase + (OV0 + (vrow + 64 * r) * 20 + vc * 4) * 4,
                  vsrc + (size_t)(64 * r) * NTOK);
        cpa16(sbase + koff0 * 4, ksrc);
        asm volatile("cp.async.commit_group;" ::: "memory");
    }
    __syncthreads();   // Q visible

    // hoist Q fragments (rows 16*w_rg)
    unsigned ah[2][4], al_q[2][4];
    {
        const unsigned* uQh = su + OQH;
        const unsigned* uQl = su + OQL;
#pragma unroll
        for (int ks = 0; ks < 2; ks++) {
            int base = (16 * w_rg + qr) * 20 + ks * 8 + quad;
            ah[ks][0] = uQh[base];       ah[ks][1] = uQh[base + 160];
            ah[ks][2] = uQh[base + 4];   ah[ks][3] = uQh[base + 164];
            al_q[ks][0] = uQl[base];     al_q[ks][1] = uQl[base + 160];
            al_q[ks][2] = uQl[base + 4]; al_q[ks][3] = uQl[base + 164];
        }
    }

    float4 acc[2][8];
#pragma unroll
    for (int s = 0; s < 2; s++)
#pragma unroll
        for (int o = 0; o < 8; o++) acc[s][o] = make_float4(0.f, 0.f, 0.f, 0.f);
    // running max + alpha replicas for this thread's 4 PV rows: m_base + 8j + qr
    float m_run[4] = {-1e4f, -1e4f, -1e4f, -1e4f};
    float alpha[4];
    float psum0 = 0.f, psum1 = 0.f;     // partial sums for S rows (j0, j0+1)
    const int j0 = (w_rg & 1) * 2;

    for (int kt = 0; kt < 128; kt++) {
        const int cur = kt & 1;
        const unsigned* uKh = su + (cur ? OKH1 : OKH0);
        const unsigned* uKl = su + (cur ? OKL1 : OKL0);
        const unsigned* uV  = su + (cur ? OV1 : OV0);

        asm volatile("cp.async.wait_group 0;" ::: "memory");
        __syncthreads();

        if (kt + 1 < 128) {
            int jn = (kt + 1) * 32;
#pragma unroll
            for (int r = 0; r < 4; r++)
                cpa16(sbase + ((cur ? OV0 : OV1) + (vrow + 64 * r) * 20 + vc * 4) * 4,
                      vsrc + jn + (size_t)(64 * r) * NTOK);
            cpa16(sbase + (cur ? koff0 : koff1) * 4, ksrc + (size_t)jn * CQ);
            asm volatile("cp.async.commit_group;" ::: "memory");
        }

        // ---- S half-tile (16 rows x 16 cols), all warps ----
        float4 creg[2];
#pragma unroll
        for (int nt = 0; nt < 2; nt++) {
            int ntg = 2 * w_h + nt;
            float4 c = make_float4(0.f, 0.f, 0.f, 0.f);
#pragma unroll
            for (int ks = 0; ks < 2; ks++) {
                int kb = (ntg * 8 + qr) * 20 + ks * 8 + quad;
                unsigned bh0 = uKh[kb], bh1 = uKh[kb + 4];
                unsigned bl0 = uKl[kb], bl1 = uKl[kb + 4];
                mma16(c, ah[ks], bh0, bh1);
                mma16(c, al_q[ks], bh0, bh1);
                mma16(c, ah[ks], bl0, bl1);
            }
            creg[nt] = c;
        }
        // local row max over this warp's 16 columns
        float lm0 = fmaxf(fmaxf(creg[0].x, creg[0].y), fmaxf(creg[1].x, creg[1].y));
        float lm1 = fmaxf(fmaxf(creg[0].z, creg[0].w), fmaxf(creg[1].z, creg[1].w));
        lm0 = fmaxf(lm0, __shfl_xor_sync(0xffffffffu, lm0, 1));
        lm0 = fmaxf(lm0, __shfl_xor_sync(0xffffffffu, lm0, 2));
        lm1 = fmaxf(lm1, __shfl_xor_sync(0xffffffffu, lm1, 1));
        lm1 = fmaxf(lm1, __shfl_xor_sync(0xffffffffu, lm1, 2));
        if (quad == 0) {
            sLm[w_h * 64 + 16 * w_rg + qr]     = lm0;
            sLm[w_h * 64 + 16 * w_rg + qr + 8] = lm1;
        }
        __syncthreads();   // local maxes visible

        // update running max + alpha replicas for this thread's 4 rows
#pragma unroll
        for (int j = 0; j < 4; j++) {
            int r = m_base + 8 * j + qr;
            float lm = fmaxf(sLm[r], sLm[64 + r]);
            float mn = fmaxf(m_run[j], lm);
            alpha[j] = ex2(m_run[j] - mn);
            m_run[j] = mn;
        }

        // exp + P store + partial sums (S rows = j0, j0+1)
        float ls0 = 0.f, ls1 = 0.f;
#pragma unroll
        for (int nt = 0; nt < 2; nt++) {
            int ntg = 2 * w_h + nt;
            float px = ex2(creg[nt].x - m_run[j0]);
            float py = ex2(creg[nt].y - m_run[j0]);
            float pz = ex2(creg[nt].z - m_run[j0 + 1]);
            float pw = ex2(creg[nt].w - m_run[j0 + 1]);
            ls0 += px + py;
            ls1 += pz + pw;
            __half2 hA = __floats2half2_rn(px, py);
            __half2 hB = __floats2half2_rn(pz, pw);
            uP[(16 * w_rg + qr) * 20 + ntg * 4 + quad]     = *(unsigned*)&hA;
            uP[(16 * w_rg + qr + 8) * 20 + ntg * 4 + quad] = *(unsigned*)&hB;
        }
        psum0 = psum0 * alpha[j0]     + ls0;
        psum1 = psum1 * alpha[j0 + 1] + ls1;

        // rescale acc by alphas (register-resident)
#pragma unroll
        for (int o = 0; o < 8; o++) {
            acc[0][o].x *= alpha[0]; acc[0][o].y *= alpha[0];
            acc[0][o].z *= alpha[1]; acc[0][o].w *= alpha[1];
            acc[1][o].x *= alpha[2]; acc[1][o].y *= alpha[2];
            acc[1][o].z *= alpha[3]; acc[1][o].w *= alpha[3];
        }
        __syncthreads();   // P ready

        // ---- PV (fp16, m16n8k16) ----
#pragma unroll
        for (int ks = 0; ks < 2; ks++) {
            unsigned p0[4], p1[4];
            int a0i = (m_base + qr) * 20 + ks * 8 + quad;
            p0[0] = uP[a0i];     p0[1] = uP[a0i + 160];
            p0[2] = uP[a0i + 4]; p0[3] = uP[a0i + 164];
            int a1i = (m_base + 16 + qr) * 20 + ks * 8 + quad;
            p1[0] = uP[a1i];     p1[1] = uP[a1i + 160];
            p1[2] = uP[a1i + 4]; p1[3] = uP[a1i + 164];
#pragma unroll
            for (int ot = 0; ot < 8; ot++) {
                int vi = (o_base + ot * 8 + qr) * 20 + ks * 8 + quad;
                unsigned v0 = uV[vi], v1 = uV[vi + 4];
                mma16(acc[0][ot], p0, v0, v1);
                mma16(acc[1][ot], p1, v0, v1);
            }
        }
    }

    // ---- combine partial denominators ----
    psum0 += __shfl_xor_sync(0xffffffffu, psum0, 1);
    psum0 += __shfl_xor_sync(0xffffffffu, psum0, 2);
    psum1 += __shfl_xor_sync(0xffffffffu, psum1, 1);
    psum1 += __shfl_xor_sync(0xffffffffu, psum1, 2);
    __syncthreads();
    if (quad == 0) {
        sSum[w_h * 64 + 16 * w_rg + qr]     = psum0;
        sSum[w_h * 64 + 16 * w_rg + qr + 8] = psum1;
    }
    __syncthreads();

    const float gm = gamma[0];
    const float* xb = x   + (size_t)b * CC * NTOK;
    float*       ob = out + (size_t)b * CC * NTOK;
#pragma unroll
    for (int s = 0; s < 2; s++) {
        int rA = m_base + 16 * s + qr;
        float scA = gm / (sSum[rA] + sSum[64 + rA]);
        float scB = gm / (sSum[rA + 8] + sSum[64 + rA + 8]);
        int m = q0 + rA;
#pragma unroll
        for (int ot = 0; ot < 8; ot++) {
            int o = o_base + ot * 8 + 2 * quad;
            float4 c = acc[s][ot];
            size_t i00 = (size_t)o * NTOK + m;
            size_t i10 = (size_t)(o + 1) * NTOK + m;
            ob[i00]     = fmaf(scA, c.x, xb[i00]);
            ob[i10]     = fmaf(scA, c.y, xb[i10]);
            ob[i00 + 8] = fmaf(scB, c.z, xb[i00 + 8]);
            ob[i10 + 8] = fmaf(scB, c.w, xb[i10 + 8]);
        }
    }
}

// ============ launch ============
extern "C" void kernel_launch(void* const* d_in, const int* in_sizes, int n_in,
                              void* d_out, int out_size)
{
    const float* x     = (const float*)d_in[0];
    const float* wq    = (const float*)d_in[1];
    const float* bq    = (const float*)d_in[2];
    const float* wk    = (const float*)d_in[3];
    const float* bk    = (const float*)d_in[4];
    const float* wv    = (const float*)d_in[5];
    const float* bv    = (const float*)d_in[6];
    const float* gamma = (const float*)d_in[7];
    float* out = (float*)d_out;

    dim3 pgrid(NTOK / 128, 5, BATCH);
    proj_kernel<<<pgrid, 256>>>(x, wq, bq, wk, bk, wv, bv);

    const int smem_bytes = SMEM_WORDS * 4;   // 67584
    cudaFuncSetAttribute(attn_kernel, cudaFuncAttributeMaxDynamicSharedMemorySize, smem_bytes);
    attn_kernel<<<BATCH * (NTOK / 64), 256, smem_bytes>>>(x, gamma, out);
}

// round 12
// speedup vs baseline: 1.0379x; 1.0379x over previous
#include <cuda_runtime.h>
#include <cuda_fp16.h>
#include <math.h>

#define BATCH 4
#define CC    256
#define CQ    32
#define NTOK  4096
#define LOG2E 1.4426950408889634f

__device__ __half g_qh[BATCH * NTOK * CQ];   // q * log2e, fp16 hi
__device__ __half g_ql[BATCH * NTOK * CQ];   // fp16 lo
__device__ __half g_kh[BATCH * NTOK * CQ];
__device__ __half g_kl[BATCH * NTOK * CQ];
__device__ __half g_vh[BATCH * CC * NTOK];   // [b][o][n] fp16

__device__ __forceinline__ void mma16(float4& d, const unsigned* a, unsigned b0, unsigned b1) {
    asm volatile(
        "mma.sync.aligned.m16n8k16.row.col.f32.f16.f16.f32 "
        "{%0,%1,%2,%3},{%4,%5,%6,%7},{%8,%9},{%0,%1,%2,%3};"
        : "+f"(d.x), "+f"(d.y), "+f"(d.z), "+f"(d.w)
        : "r"(a[0]), "r"(a[1]), "r"(a[2]), "r"(a[3]), "r"(b0), "r"(b1));
}
__device__ __forceinline__ void cpa16(unsigned dst, const void* src) {
    asm volatile("cp.async.ca.shared.global [%0], [%1], 16;" :: "r"(dst), "l"(src));
}
__device__ __forceinline__ float ex2(float x) {
    float r; asm("ex2.approx.f32 %0, %1;" : "=f"(r) : "f"(x)); return r;
}

// ============ Kernel 1: projections + fp16 layout production ============
__global__ __launch_bounds__(256) void proj_kernel(
    const float* __restrict__ x,
    const float* __restrict__ wq, const float* __restrict__ bq,
    const float* __restrict__ wk, const float* __restrict__ bk,
    const float* __restrict__ wv, const float* __restrict__ bv)
{
    __shared__ float sX[32 * 128];
    __shared__ float sW[32 * 68];
    const int n0 = blockIdx.x * 128, r0 = blockIdx.y * 64, b = blockIdx.z;
    const int t = threadIdx.x, rg = t >> 4, ng = t & 15;
    float acc[4][8];
#pragma unroll
    for (int j = 0; j < 4; j++)
#pragma unroll
        for (int i = 0; i < 8; i++) acc[j][i] = 0.0f;
    for (int cc = 0; cc < CC; cc += 32) {
#pragma unroll
        for (int p = 0; p < 4; p++) {
            int idx = p * 256 + t, cr = idx >> 5, l = idx & 31;
            float4 v = *(const float4*)(x + ((size_t)b * CC + cc + cr) * NTOK + n0 + 4 * l);
            *(float4*)(sX + cr * 128 + 4 * l) = v;
        }
#pragma unroll
        for (int p = 0; p < 2; p++) {
            int idx = p * 256 + t, rl = idx >> 3, cf = idx & 7;
            int rglob = r0 + rl;
            const float* wrow;
            if (rglob < CQ)          wrow = wq + (size_t)rglob * CC;
            else if (rglob < 2 * CQ) wrow = wk + (size_t)(rglob - CQ) * CC;
            else                     wrow = wv + (size_t)(rglob - 2 * CQ) * CC;
            float4 v = *(const float4*)(wrow + cc + 4 * cf);
            sW[(4 * cf + 0) * 68 + rl] = v.x;
            sW[(4 * cf + 1) * 68 + rl] = v.y;
            sW[(4 * cf + 2) * 68 + rl] = v.z;
            sW[(4 * cf + 3) * 68 + rl] = v.w;
        }
        __syncthreads();
#pragma unroll
        for (int c = 0; c < 32; c++) {
            float4 w  = *(float4*)(sW + c * 68 + 4 * rg);
            float4 x1 = *(float4*)(sX + c * 128 + 4 * ng);
            float4 x2 = *(float4*)(sX + c * 128 + 64 + 4 * ng);
            float wj[4] = {w.x, w.y, w.z, w.w};
            float xs[8] = {x1.x, x1.y, x1.z, x1.w, x2.x, x2.y, x2.z, x2.w};
#pragma unroll
            for (int j = 0; j < 4; j++)
#pragma unroll
                for (int i = 0; i < 8; i++) acc[j][i] = fmaf(wj[j], xs[i], acc[j][i]);
        }
        __syncthreads();
    }
#pragma unroll
    for (int j = 0; j < 4; j++) {
        int rglob = r0 + 4 * rg + j;
        if (rglob < 2 * CQ) {
            bool isq = rglob < CQ;
            int c = isq ? rglob : rglob - CQ;
            float bias = isq ? bq[c] : bk[c];
            float scale = isq ? LOG2E : 1.0f;
            __half* dh = (isq ? g_qh : g_kh) + (size_t)b * NTOK * CQ + c;
            __half* dl = (isq ? g_ql : g_kl) + (size_t)b * NTOK * CQ + c;
#pragma unroll
            for (int i = 0; i < 8; i++) {
                int n = (i < 4) ? (n0 + 4 * ng + i) : (n0 + 64 + 4 * ng + i - 4);
                float v = (acc[j][i] + bias) * scale;
                __half h = __float2half_rn(v);
                dh[(size_t)n * CQ] = h;
                dl[(size_t)n * CQ] = __float2half_rn(v - __half2float(h));
            }
        } else {
            int o = rglob - 2 * CQ;
            float bias = bv[o];
            __half* dst = g_vh + ((size_t)b * CC + o) * NTOK;
            __half2 h0 = __floats2half2_rn(acc[j][0] + bias, acc[j][1] + bias);
            __half2 h1 = __floats2half2_rn(acc[j][2] + bias, acc[j][3] + bias);
            __half2 h2 = __floats2half2_rn(acc[j][4] + bias, acc[j][5] + bias);
            __half2 h3 = __floats2half2_rn(acc[j][6] + bias, acc[j][7] + bias);
            *(__half2*)(dst + n0 + 4 * ng)          = h0;
            *(__half2*)(dst + n0 + 4 * ng + 2)      = h1;
            *(__half2*)(dst + n0 + 64 + 4 * ng)     = h2;
            *(__half2*)(dst + n0 + 64 + 4 * ng + 2) = h3;
        }
    }
}

// ============ Kernel 2: flash attention, ping-pong S/softmax groups ============
#define OQH  0
#define OQL  1280
#define OKH0 2560
#define OKL0 3200
#define OKH1 3840
#define OKL1 4480
#define OV0  5120
#define OV1  10240
#define OP   15360
#define OSUM 16640
#define OAL  16704
#define OM   16768
#define SMEM_WORDS 16832

#define S_COMPUTE(CR, KH, KL)                                              \
    do {                                                                   \
        _Pragma("unroll")                                                  \
        for (int nt = 0; nt < 4; nt++) {                                   \
            float4 c = make_float4(0.f, 0.f, 0.f, 0.f);                    \
            _Pragma("unroll")                                              \
            for (int ks = 0; ks < 2; ks++) {                               \
                int kb = (nt * 8 + qr) * 20 + ks * 8 + quad;               \
                unsigned bh0 = (KH)[kb], bh1 = (KH)[kb + 4];               \
                unsigned bl0 = (KL)[kb], bl1 = (KL)[kb + 4];               \
                mma16(c, ah[ks], bh0, bh1);                                \
                mma16(c, alq[ks], bh0, bh1);                               \
                mma16(c, ah[ks], bl0, bl1);                                \
            }                                                              \
            (CR)[nt] = c;                                                  \
        }                                                                  \
    } while (0)

__global__ __launch_bounds__(256, 2) void attn_kernel(
    const float* __restrict__ x,
    const float* __restrict__ gamma,
    float* __restrict__ out)
{
    extern __shared__ unsigned su[];
    unsigned* uP = su + OP;
    float* sSum = (float*)(su + OSUM);
    float* sAl  = (float*)(su + OAL);
    float* sM   = (float*)(su + OM);

    const int t = threadIdx.x, w = t >> 5, lane = t & 31;
    const int quad = lane & 3, qr = lane >> 2;
    const int g = w >> 2;                 // ping-pong group
    const int r0s = 16 * (w & 3);         // S/softmax row strip
    const int m_base = 32 * g, o_base = 64 * (w & 3);   // PV map
    const int b = blockIdx.x >> 6, q0 = (blockIdx.x & 63) * 64;
    const unsigned sbase = (unsigned)__cvta_generic_to_shared(su);

    const __half* khp = g_kh + (size_t)b * NTOK * CQ;
    const __half* klp = g_kl + (size_t)b * NTOK * CQ;
    const __half* vb  = g_vh + (size_t)b * CC * NTOK;

    // Q staging + row-state init
    {
        int r = t >> 2, qw = t & 3;
        size_t off = ((size_t)b * NTOK + q0 + r) * CQ + qw * 8;
        *(uint4*)(su + OQH + r * 20 + qw * 4) = *(const uint4*)(g_qh + off);
        *(uint4*)(su + OQL + r * 20 + qw * 4) = *(const uint4*)(g_ql + off);
    }
    if (t < 64) { sM[t] = -1e4f; sSum[t] = 0.f; }

    // cp.async plumbing (as round 9)
    const int vc = t & 3, vrow = t >> 2;
    const __half* vsrc = vb + (size_t)vrow * NTOK + vc * 8;
    const int krow = (t >> 2) & 31, kc = t & 3;
    const __half* ksrc = ((t < 128) ? khp : klp) + (size_t)krow * CQ + kc * 8;
    const unsigned koff0 = ((t < 128) ? OKH0 : OKL0) + krow * 20 + kc * 4;
    const unsigned koff1 = ((t < 128) ? OKH1 : OKL1) + krow * 20 + kc * 4;

    // prologue: K(0) alone; then {V(0), K(1)}
    cpa16(sbase + koff0 * 4, ksrc);
    asm volatile("cp.async.commit_group;" ::: "memory");
#pragma unroll
    for (int r = 0; r < 4; r++)
        cpa16(sbase + (OV0 + (vrow + 64 * r) * 20 + vc * 4) * 4,
              vsrc + (size_t)(64 * r) * NTOK);
    cpa16(sbase + koff1 * 4, ksrc + (size_t)32 * CQ);
    asm volatile("cp.async.commit_group;" ::: "memory");
    asm volatile("cp.async.wait_group 1;" ::: "memory");
    __syncthreads();   // Q + inits + K(0) visible

    // hoist Q fragments for rows r0s
    unsigned ah[2][4], alq[2][4];
    {
        const unsigned* uQh = su + OQH;
        const unsigned* uQl = su + OQL;
#pragma unroll
        for (int ks = 0; ks < 2; ks++) {
            int base = (r0s + qr) * 20 + ks * 8 + quad;
            ah[ks][0] = uQh[base];      ah[ks][1] = uQh[base + 160];
            ah[ks][2] = uQh[base + 4];  ah[ks][3] = uQh[base + 164];
            alq[ks][0] = uQl[base];     alq[ks][1] = uQl[base + 160];
            alq[ks][2] = uQl[base + 4]; alq[ks][3] = uQl[base + 164];
        }
    }

    float4 acc[2][8];
#pragma unroll
    for (int s = 0; s < 2; s++)
#pragma unroll
        for (int o = 0; o < 8; o++) acc[s][o] = make_float4(0.f, 0.f, 0.f, 0.f);

    float4 creg[4];
    if (g == 0) S_COMPUTE(creg, su + OKH0, su + OKL0);   // S(0)

    for (int kt = 0; kt < 128; kt++) {
        asm volatile("cp.async.wait_group 0;" ::: "memory");
        __syncthreads();   // V(kt), K(kt+1) visible; prev P/buffers consumed

        // issue {V(kt+1) -> buf (kt+1)&1, K(kt+2) -> buf kt&1}
        if (kt + 1 < 128) {
            int jn = (kt + 1) * 32;
            unsigned vo = (kt & 1) ? OV0 : OV1;
#pragma unroll
            for (int r = 0; r < 4; r++)
                cpa16(sbase + (vo + (vrow + 64 * r) * 20 + vc * 4) * 4,
                      vsrc + jn + (size_t)(64 * r) * NTOK);
            if (kt + 2 < 128)
                cpa16(sbase + ((kt & 1) ? koff1 : koff0) * 4,
                      ksrc + (size_t)(jn + 32) * CQ);
        }
        asm volatile("cp.async.commit_group;" ::: "memory");

        if (g == (kt & 1)) {
            // softmax of S(kt) held in creg
            float lm0 = -1e30f, lm1 = -1e30f;
#pragma unroll
            for (int nt = 0; nt < 4; nt++) {
                lm0 = fmaxf(lm0, fmaxf(creg[nt].x, creg[nt].y));
                lm1 = fmaxf(lm1, fmaxf(creg[nt].z, creg[nt].w));
            }
            lm0 = fmaxf(lm0, __shfl_xor_sync(0xffffffffu, lm0, 1));
            lm0 = fmaxf(lm0, __shfl_xor_sync(0xffffffffu, lm0, 2));
            lm1 = fmaxf(lm1, __shfl_xor_sync(0xffffffffu, lm1, 1));
            lm1 = fmaxf(lm1, __shfl_xor_sync(0xffffffffu, lm1, 2));
            int r = r0s + qr, r2 = r + 8;
            float mO0 = sM[r], mO1 = sM[r2];
            float mN0 = fmaxf(mO0, lm0), mN1 = fmaxf(mO1, lm1);
            float a0 = ex2(mO0 - mN0), a1 = ex2(mO1 - mN1);
            float ls0 = 0.f, ls1 = 0.f;
#pragma unroll
            for (int nt = 0; nt < 4; nt++) {
                float px = ex2(creg[nt].x - mN0), py = ex2(creg[nt].y - mN0);
                float pz = ex2(creg[nt].z - mN1), pw = ex2(creg[nt].w - mN1);
                ls0 += px + py; ls1 += pz + pw;
                __half2 hA = __floats2half2_rn(px, py);
                __half2 hB = __floats2half2_rn(pz, pw);
                uP[r * 20 + nt * 4 + quad]  = *(unsigned*)&hA;
                uP[r2 * 20 + nt * 4 + quad] = *(unsigned*)&hB;
            }
            ls0 += __shfl_xor_sync(0xffffffffu, ls0, 1);
            ls0 += __shfl_xor_sync(0xffffffffu, ls0, 2);
            ls1 += __shfl_xor_sync(0xffffffffu, ls1, 1);
            ls1 += __shfl_xor_sync(0xffffffffu, ls1, 2);
            if (quad == 0) {
                sM[r] = mN0; sM[r2] = mN1;
                sAl[r] = a0; sAl[r2] = a1;
                sSum[r]  = sSum[r]  * a0 + ls0;
                sSum[r2] = sSum[r2] * a1 + ls1;
            }
        } else if (kt + 1 < 128) {
            // compute S(kt+1) from K buffer (kt+1)&1
            const unsigned* kh = su + (((kt + 1) & 1) ? OKH1 : OKH0);
            const unsigned* kl = su + (((kt + 1) & 1) ? OKL1 : OKL0);
            S_COMPUTE(creg, kh, kl);
        }
        __syncthreads();   // P(kt) + alphas ready

        // rescale + PV from V buffer kt&1
        const unsigned* uV = su + ((kt & 1) ? OV1 : OV0);
        float aA0 = sAl[m_base + qr],      aB0 = sAl[m_base + qr + 8];
        float aA1 = sAl[m_base + 16 + qr], aB1 = sAl[m_base + 24 + qr];
#pragma unroll
        for (int o = 0; o < 8; o++) {
            acc[0][o].x *= aA0; acc[0][o].y *= aA0; acc[0][o].z *= aB0; acc[0][o].w *= aB0;
            acc[1][o].x *= aA1; acc[1][o].y *= aA1; acc[1][o].z *= aB1; acc[1][o].w *= aB1;
        }
#pragma unroll
        for (int ks = 0; ks < 2; ks++) {
            unsigned p0[4], p1[4];
            int a0i = (m_base + qr) * 20 + ks * 8 + quad;
            p0[0] = uP[a0i];     p0[1] = uP[a0i + 160];
            p0[2] = uP[a0i + 4]; p0[3] = uP[a0i + 164];
            int a1i = (m_base + 16 + qr) * 20 + ks * 8 + quad;
            p1[0] = uP[a1i];     p1[1] = uP[a1i + 160];
            p1[2] = uP[a1i + 4]; p1[3] = uP[a1i + 164];
#pragma unroll
            for (int ot = 0; ot < 8; ot++) {
                int vi = (o_base + ot * 8 + qr) * 20 + ks * 8 + quad;
                unsigned v0 = uV[vi], v1 = uV[vi + 4];
                mma16(acc[0][ot], p0, v0, v1);
                mma16(acc[1][ot], p1, v0, v1);
            }
        }
    }

    // epilogue: sSum is the complete denominator per row
    const float gm = gamma[0];
    const float* xb = x   + (size_t)b * CC * NTOK;
    float*       ob = out + (size_t)b * CC * NTOK;
#pragma unroll
    for (int s = 0; s < 2; s++) {
        int rA = m_base + 16 * s + qr;
        float scA = gm / sSum[rA];
        float scB = gm / sSum[rA + 8];
        int m = q0 + rA;
#pragma unroll
        for (int ot = 0; ot < 8; ot++) {
            int o = o_base + ot * 8 + 2 * quad;
            float4 c = acc[s][ot];
            size_t i00 = (size_t)o * NTOK + m;
            size_t i10 = (size_t)(o + 1) * NTOK + m;
            ob[i00]     = fmaf(scA, c.x, xb[i00]);
            ob[i10]     = fmaf(scA, c.y, xb[i10]);
            ob[i00 + 8] = fmaf(scB, c.z, xb[i00 + 8]);
            ob[i10 + 8] = fmaf(scB, c.w, xb[i10 + 8]);
        }
    }
}

// ============ launch ============
extern "C" void kernel_launch(void* const* d_in, const int* in_sizes, int n_in,
                              void* d_out, int out_size)
{
    const float* x     = (const float*)d_in[0];
    const float* wq    = (const float*)d_in[1];
    const float* bq    = (const float*)d_in[2];
    const float* wk    = (const float*)d_in[3];
    const float* bk    = (const float*)d_in[4];
    const float* wv    = (const float*)d_in[5];
    const float* bv    = (const float*)d_in[6];
    const float* gamma = (const float*)d_in[7];
    float* out = (float*)d_out;

    dim3 pgrid(NTOK / 128, 5, BATCH);
    proj_kernel<<<pgrid, 256>>>(x, wq, bq, wk, bk, wv, bv);

    const int smem_bytes = SMEM_WORDS * 4;   // 67328
    cudaFuncSetAttribute(attn_kernel, cudaFuncAttributeMaxDynamicSharedMemorySize, smem_bytes);
    attn_kernel<<<BATCH * (NTOK / 64), 256, smem_bytes>>>(x, gamma, out);
}

// round 13
// speedup vs baseline: 1.3419x; 1.2929x over previous
#include <cuda_runtime.h>
#include <cuda_fp16.h>
#include <math.h>

#define BATCH 4
#define CC    256
#define CQ    32
#define NTOK  4096
#define LOG2E 1.4426950408889634f

__device__ __half g_qh[BATCH * NTOK * CQ];   // q * log2e, fp16 hi
__device__ __half g_ql[BATCH * NTOK * CQ];   // fp16 lo
__device__ __half g_kh[BATCH * NTOK * CQ];   // k fp16 (hi only)
__device__ __half g_vh[BATCH * CC * NTOK];   // [b][o][n] fp16

__device__ __forceinline__ void mma16(float4& d, const unsigned* a, unsigned b0, unsigned b1) {
    asm volatile(
        "mma.sync.aligned.m16n8k16.row.col.f32.f16.f16.f32 "
        "{%0,%1,%2,%3},{%4,%5,%6,%7},{%8,%9},{%0,%1,%2,%3};"
        : "+f"(d.x), "+f"(d.y), "+f"(d.z), "+f"(d.w)
        : "r"(a[0]), "r"(a[1]), "r"(a[2]), "r"(a[3]), "r"(b0), "r"(b1));
}
__device__ __forceinline__ void cpa16(unsigned dst, const void* src) {
    asm volatile("cp.async.ca.shared.global [%0], [%1], 16;" :: "r"(dst), "l"(src));
}
__device__ __forceinline__ float ex2(float x) {
    float r; asm("ex2.approx.f32 %0, %1;" : "=f"(r) : "f"(x)); return r;
}

// ============ Kernel 1: projections + fp16 layout production ============
__global__ __launch_bounds__(256) void proj_kernel(
    const float* __restrict__ x,
    const float* __restrict__ wq, const float* __restrict__ bq,
    const float* __restrict__ wk, const float* __restrict__ bk,
    const float* __restrict__ wv, const float* __restrict__ bv)
{
    __shared__ float sX[32 * 128];
    __shared__ float sW[32 * 68];
    const int n0 = blockIdx.x * 128, r0 = blockIdx.y * 64, b = blockIdx.z;
    const int t = threadIdx.x, rg = t >> 4, ng = t & 15;
    float acc[4][8];
#pragma unroll
    for (int j = 0; j < 4; j++)
#pragma unroll
        for (int i = 0; i < 8; i++) acc[j][i] = 0.0f;
    for (int cc = 0; cc < CC; cc += 32) {
#pragma unroll
        for (int p = 0; p < 4; p++) {
            int idx = p * 256 + t, cr = idx >> 5, l = idx & 31;
            float4 v = *(const float4*)(x + ((size_t)b * CC + cc + cr) * NTOK + n0 + 4 * l);
            *(float4*)(sX + cr * 128 + 4 * l) = v;
        }
#pragma unroll
        for (int p = 0; p < 2; p++) {
            int idx = p * 256 + t, rl = idx >> 3, cf = idx & 7;
            int rglob = r0 + rl;
            const float* wrow;
            if (rglob < CQ)          wrow = wq + (size_t)rglob * CC;
            else if (rglob < 2 * CQ) wrow = wk + (size_t)(rglob - CQ) * CC;
            else                     wrow = wv + (size_t)(rglob - 2 * CQ) * CC;
            float4 v = *(const float4*)(wrow + cc + 4 * cf);
            sW[(4 * cf + 0) * 68 + rl] = v.x;
            sW[(4 * cf + 1) * 68 + rl] = v.y;
            sW[(4 * cf + 2) * 68 + rl] = v.z;
            sW[(4 * cf + 3) * 68 + rl] = v.w;
        }
        __syncthreads();
#pragma unroll
        for (int c = 0; c < 32; c++) {
            float4 w  = *(float4*)(sW + c * 68 + 4 * rg);
            float4 x1 = *(float4*)(sX + c * 128 + 4 * ng);
            float4 x2 = *(float4*)(sX + c * 128 + 64 + 4 * ng);
            float wj[4] = {w.x, w.y, w.z, w.w};
            float xs[8] = {x1.x, x1.y, x1.z, x1.w, x2.x, x2.y, x2.z, x2.w};
#pragma unroll
            for (int j = 0; j < 4; j++)
#pragma unroll
                for (int i = 0; i < 8; i++) acc[j][i] = fmaf(wj[j], xs[i], acc[j][i]);
        }
        __syncthreads();
    }
#pragma unroll
    for (int j = 0; j < 4; j++) {
        int rglob = r0 + 4 * rg + j;
        if (rglob < CQ) {
            int c = rglob;
            float bias = bq[c];
            __half* dh = g_qh + (size_t)b * NTOK * CQ + c;
            __half* dl = g_ql + (size_t)b * NTOK * CQ + c;
#pragma unroll
            for (int i = 0; i < 8; i++) {
                int n = (i < 4) ? (n0 + 4 * ng + i) : (n0 + 64 + 4 * ng + i - 4);
                float v = (acc[j][i] + bias) * LOG2E;
                __half h = __float2half_rn(v);
                dh[(size_t)n * CQ] = h;
                dl[(size_t)n * CQ] = __float2half_rn(v - __half2float(h));
            }
        } else if (rglob < 2 * CQ) {
            int c = rglob - CQ;
            float bias = bk[c];
            __half* dh = g_kh + (size_t)b * NTOK * CQ + c;
#pragma unroll
            for (int i = 0; i < 8; i++) {
                int n = (i < 4) ? (n0 + 4 * ng + i) : (n0 + 64 + 4 * ng + i - 4);
                dh[(size_t)n * CQ] = __float2half_rn(acc[j][i] + bias);
            }
        } else {
            int o = rglob - 2 * CQ;
            float bias = bv[o];
            __half* dst = g_vh + ((size_t)b * CC + o) * NTOK;
            __half2 h0 = __floats2half2_rn(acc[j][0] + bias, acc[j][1] + bias);
            __half2 h1 = __floats2half2_rn(acc[j][2] + bias, acc[j][3] + bias);
            __half2 h2 = __floats2half2_rn(acc[j][4] + bias, acc[j][5] + bias);
            __half2 h3 = __floats2half2_rn(acc[j][6] + bias, acc[j][7] + bias);
            *(__half2*)(dst + n0 + 4 * ng)          = h0;
            *(__half2*)(dst + n0 + 4 * ng + 2)      = h1;
            *(__half2*)(dst + n0 + 64 + 4 * ng)     = h2;
            *(__half2*)(dst + n0 + 64 + 4 * ng + 2) = h3;
        }
    }
}

// ============ Kernel 2: flash attention, 64-key tiles ============
// words: Q hi [0,1280) lo [1280,2560) -- P [64][36]=2304 aliases it after hoist
#define OQH  0
#define OQL  1280
#define OP   0
#define OKH0 2560
#define OKH1 3840
#define OV0  5120
#define OV1  14336
#define OAL  23552
#define OSC  23616
#define SMEM_WORDS 23680

__global__ __launch_bounds__(256, 2) void attn_kernel(
    const float* __restrict__ x,
    const float* __restrict__ gamma,
    float* __restrict__ out)
{
    extern __shared__ unsigned su[];
    unsigned* uP = su + OP;
    float* sAl = (float*)(su + OAL);
    float* sSc = (float*)(su + OSC);

    const int t = threadIdx.x, w = t >> 5, lane = t & 31;
    const int quad = lane & 3, qr = lane >> 2;
    const int m_base = 32 * (w >> 2), o_base = 64 * (w & 3);
    const int b = blockIdx.x >> 6, q0 = (blockIdx.x & 63) * 64;
    const unsigned sbase = (unsigned)__cvta_generic_to_shared(su);

    const __half* khp = g_kh + (size_t)b * NTOK * CQ;
    const __half* vb  = g_vh + (size_t)b * CC * NTOK;

    // ---- Q staging ----
    {
        int r = t >> 2, qw = t & 3;
        size_t off = ((size_t)b * NTOK + q0 + r) * CQ + qw * 8;
        *(uint4*)(su + OQH + r * 20 + qw * 4) = *(const uint4*)(g_qh + off);
        *(uint4*)(su + OQL + r * 20 + qw * 4) = *(const uint4*)(g_ql + off);
    }

    // ---- cp.async plumbing: 64-key tiles ----
    const int kr = t >> 2, kc = t & 3;              // K: 64 rows x 4 chunks
    const __half* ksrc = khp + (size_t)kr * CQ + kc * 8;
    const unsigned koff = kr * 20 + kc * 4;
    const int vrow = t >> 3, vci = t & 7;           // V: orow = vrow + 32r, 8 chunks/row
    const __half* vsrc = vb + (size_t)vrow * NTOK + vci * 8;
    const unsigned voff = vrow * 36 + vci * 4;

    // prologue: tile 0 -> buffer 0
#pragma unroll
    for (int r = 0; r < 8; r++)
        cpa16(sbase + (OV0 + voff + (32 * r) * 36) * 4, vsrc + (size_t)(32 * r) * NTOK);
    cpa16(sbase + (OKH0 + koff) * 4, ksrc);
    asm volatile("cp.async.commit_group;" ::: "memory");
    asm volatile("cp.async.wait_group 0;" ::: "memory");
    __syncthreads();   // Q + tile 0 visible

    // hoist Q fragments (softmax warps, rows 16w)
    unsigned ah[2][4], alq[2][4];
    if (w < 4) {
        const unsigned* uQh = su + OQH;
        const unsigned* uQl = su + OQL;
#pragma unroll
        for (int ks = 0; ks < 2; ks++) {
            int base = (16 * w + qr) * 20 + ks * 8 + quad;
            ah[ks][0] = uQh[base];      ah[ks][1] = uQh[base + 160];
            ah[ks][2] = uQh[base + 4];  ah[ks][3] = uQh[base + 164];
            alq[ks][0] = uQl[base];     alq[ks][1] = uQl[base + 160];
            alq[ks][2] = uQl[base + 4]; alq[ks][3] = uQl[base + 164];
        }
    }

    float4 acc[2][8];
#pragma unroll
    for (int s = 0; s < 2; s++)
#pragma unroll
        for (int o = 0; o < 8; o++) acc[s][o] = make_float4(0.f, 0.f, 0.f, 0.f);
    float run_m0 = -1e4f, run_m1 = -1e4f, run_l0 = 0.f, run_l1 = 0.f;

    for (int kt = 0; kt < 64; kt++) {
        const int cur = kt & 1;
        const unsigned* uKh = su + (cur ? OKH1 : OKH0);
        const unsigned* uV  = su + (cur ? OV1 : OV0);

        // issue tile kt+1 into other buffer
        if (kt + 1 < 64) {
            int jn = (kt + 1) * 64;
            unsigned vo = cur ? OV0 : OV1;
            unsigned ko = cur ? OKH0 : OKH1;
#pragma unroll
            for (int r = 0; r < 8; r++)
                cpa16(sbase + (vo + voff + (32 * r) * 36) * 4,
                      vsrc + jn + (size_t)(32 * r) * NTOK);
            cpa16(sbase + (ko + koff) * 4, ksrc + (size_t)jn * CQ);
            asm volatile("cp.async.commit_group;" ::: "memory");
        }

        if (w < 4) {   // S (16 rows x 64 cols) + online softmax
            float4 sreg[8];
#pragma unroll
            for (int nt = 0; nt < 8; nt++) {
                float4 c = make_float4(0.f, 0.f, 0.f, 0.f);
#pragma unroll
                for (int ks = 0; ks < 2; ks++) {
                    int kb = (nt * 8 + qr) * 20 + ks * 8 + quad;
                    unsigned bh0 = uKh[kb], bh1 = uKh[kb + 4];
                    mma16(c, ah[ks], bh0, bh1);
                    mma16(c, alq[ks], bh0, bh1);
                }
                sreg[nt] = c;
            }
            float mA = -1e30f, mB = -1e30f;
#pragma unroll
            for (int nt = 0; nt < 8; nt++) {
                mA = fmaxf(mA, fmaxf(sreg[nt].x, sreg[nt].y));
                mB = fmaxf(mB, fmaxf(sreg[nt].z, sreg[nt].w));
            }
            mA = fmaxf(mA, __shfl_xor_sync(0xffffffffu, mA, 1));
            mA = fmaxf(mA, __shfl_xor_sync(0xffffffffu, mA, 2));
            mB = fmaxf(mB, __shfl_xor_sync(0xffffffffu, mB, 1));
            mB = fmaxf(mB, __shfl_xor_sync(0xffffffffu, mB, 2));
            float mAn = fmaxf(run_m0, mA), mBn = fmaxf(run_m1, mB);
            float alA = ex2(run_m0 - mAn), alB = ex2(run_m1 - mBn);
            run_m0 = mAn; run_m1 = mBn;
            float sA = 0.f, sB = 0.f;
            int rw = 16 * w + qr;
#pragma unroll
            for (int nt = 0; nt < 8; nt++) {
                float px = ex2(sreg[nt].x - mAn), py = ex2(sreg[nt].y - mAn);
                float pz = ex2(sreg[nt].z - mBn), pw = ex2(sreg[nt].w - mBn);
                sA += px + py; sB += pz + pw;
                __half2 hA = __floats2half2_rn(px, py);
                __half2 hB = __floats2half2_rn(pz, pw);
                uP[rw * 36 + nt * 4 + quad]       = *(unsigned*)&hA;
                uP[(rw + 8) * 36 + nt * 4 + quad] = *(unsigned*)&hB;
            }
            sA += __shfl_xor_sync(0xffffffffu, sA, 1);
            sA += __shfl_xor_sync(0xffffffffu, sA, 2);
            sB += __shfl_xor_sync(0xffffffffu, sB, 1);
            sB += __shfl_xor_sync(0xffffffffu, sB, 2);
            run_l0 = run_l0 * alA + sA;
            run_l1 = run_l1 * alB + sB;
            if (quad == 0) { sAl[rw] = alA; sAl[rw + 8] = alB; }
        }
        __syncthreads();   // P + alphas ready

        // rescale + PV (ks 0..3 over 64 keys)
        float aA0 = sAl[m_base + qr],      aB0 = sAl[m_base + qr + 8];
        float aA1 = sAl[m_base + 16 + qr], aB1 = sAl[m_base + 24 + qr];
#pragma unroll
        for (int o = 0; o < 8; o++) {
            acc[0][o].x *= aA0; acc[0][o].y *= aA0; acc[0][o].z *= aB0; acc[0][o].w *= aB0;
            acc[1][o].x *= aA1; acc[1][o].y *= aA1; acc[1][o].z *= aB1; acc[1][o].w *= aB1;
        }
#pragma unroll
        for (int ks = 0; ks < 4; ks++) {
            unsigned p0[4], p1[4];
            int a0i = (m_base + qr) * 36 + ks * 8 + quad;
            p0[0] = uP[a0i];     p0[1] = uP[a0i + 8 * 36];
            p0[2] = uP[a0i + 4]; p0[3] = uP[a0i + 8 * 36 + 4];
            int a1i = (m_base + 16 + qr) * 36 + ks * 8 + quad;
            p1[0] = uP[a1i];     p1[1] = uP[a1i + 8 * 36];
            p1[2] = uP[a1i + 4]; p1[3] = uP[a1i + 8 * 36 + 4];
#pragma unroll
            for (int ot = 0; ot < 8; ot++) {
                int vi = (o_base + ot * 8 + qr) * 36 + ks * 8 + quad;
                unsigned v0 = uV[vi], v1 = uV[vi + 4];
                mma16(acc[0][ot], p0, v0, v1);
                mma16(acc[1][ot], p1, v0, v1);
            }
        }

        asm volatile("cp.async.wait_group 0;" ::: "memory");
        __syncthreads();   // next tile ready; P/V consumed
    }

    if (w < 4 && quad == 0) {
        float gm = gamma[0];
        sSc[16 * w + qr]     = gm / run_l0;
        sSc[16 * w + qr + 8] = gm / run_l1;
    }
    __syncthreads();

    const float gm2 = 0.f;  (void)gm2;
    const float* xb = x   + (size_t)b * CC * NTOK;
    float*       ob = out + (size_t)b * CC * NTOK;
#pragma unroll
    for (int s = 0; s < 2; s++) {
        int rA = m_base + 16 * s + qr;
        float scA = sSc[rA];
        float scB = sSc[rA + 8];
        int m = q0 + rA;
#pragma unroll
        for (int ot = 0; ot < 8; ot++) {
            int o = o_base + ot * 8 + 2 * quad;
            float4 c = acc[s][ot];
            size_t i00 = (size_t)o * NTOK + m;
            size_t i10 = (size_t)(o + 1) * NTOK + m;
            ob[i00]     = fmaf(scA, c.x, xb[i00]);
            ob[i10]     = fmaf(scA, c.y, xb[i10]);
            ob[i00 + 8] = fmaf(scB, c.z, xb[i00 + 8]);
            ob[i10 + 8] = fmaf(scB, c.w, xb[i10 + 8]);
        }
    }
}

// ============ launch ============
extern "C" void kernel_launch(void* const* d_in, const int* in_sizes, int n_in,
                              void* d_out, int out_size)
{
    const float* x     = (const float*)d_in[0];
    const float* wq    = (const float*)d_in[1];
    const float* bq    = (const float*)d_in[2];
    const float* wk    = (const float*)d_in[3];
    const float* bk    = (const float*)d_in[4];
    const float* wv    = (const float*)d_in[5];
    const float* bv    = (const float*)d_in[6];
    const float* gamma = (const float*)d_in[7];
    float* out = (float*)d_out;

    dim3 pgrid(NTOK / 128, 5, BATCH);
    proj_kernel<<<pgrid, 256>>>(x, wq, bq, wk, bk, wv, bv);

    const int smem_bytes = SMEM_WORDS * 4;   // 94720
    cudaFuncSetAttribute(attn_kernel, cudaFuncAttributeMaxDynamicSharedMemorySize, smem_bytes);
    attn_kernel<<<BATCH * (NTOK / 64), 256, smem_bytes>>>(x, gamma, out);
}

// round 15
// speedup vs baseline: 1.5536x; 1.1578x over previous
#include <cuda_runtime.h>
#include <cuda_fp16.h>
#include <math.h>

#define BATCH 4
#define CC    256
#define CQ    32
#define NTOK  4096
#define LOG2E 1.4426950408889634f

__device__ __half g_qh[BATCH * NTOK * CQ];
__device__ __half g_ql[BATCH * NTOK * CQ];
__device__ __half g_kh[BATCH * NTOK * CQ];
__device__ __half g_vh[BATCH * CC * NTOK];
__device__ __half g_xh[BATCH * NTOK * CC];
__device__ __half g_xl[BATCH * NTOK * CC];
__device__ __half g_wh[320 * CC];
__device__ __half g_wl[320 * CC];
__device__ float  g_bias[320];

__device__ __forceinline__ void mma16(float4& d, const unsigned* a, unsigned b0, unsigned b1) {
    asm volatile(
        "mma.sync.aligned.m16n8k16.row.col.f32.f16.f16.f32 "
        "{%0,%1,%2,%3},{%4,%5,%6,%7},{%8,%9},{%0,%1,%2,%3};"
        : "+f"(d.x), "+f"(d.y), "+f"(d.z), "+f"(d.w)
        : "r"(a[0]), "r"(a[1]), "r"(a[2]), "r"(a[3]), "r"(b0), "r"(b1));
}
__device__ __forceinline__ void cpa16(unsigned dst, const void* src) {
    asm volatile("cp.async.ca.shared.global [%0], [%1], 16;" :: "r"(dst), "l"(src));
}
__device__ __forceinline__ float ex2(float x) {
    float r; asm("ex2.approx.f32 %0, %1;" : "=f"(r) : "f"(x)); return r;
}

// ============ Kernel A: weight convert (hi/lo fp16, q rows pre-scaled) ============
__global__ __launch_bounds__(256) void convw_kernel(
    const float* __restrict__ wq, const float* __restrict__ bq,
    const float* __restrict__ wk, const float* __restrict__ bk,
    const float* __restrict__ wv, const float* __restrict__ bv)
{
    int row = blockIdx.x, t = threadIdx.x;
    float scale = (row < CQ) ? LOG2E : 1.0f;
    const float* src;
    if (row < CQ)          src = wq + (size_t)row * CC;
    else if (row < 2 * CQ) src = wk + (size_t)(row - CQ) * CC;
    else                   src = wv + (size_t)(row - 2 * CQ) * CC;
    float v = src[t] * scale;
    __half h = __float2half_rn(v);
    g_wh[row * CC + t] = h;
    g_wl[row * CC + t] = __float2half_rn(v - __half2float(h));
    if (t == 0) {
        float bb = (row < CQ) ? bq[row] : (row < 2 * CQ) ? bk[row - CQ] : bv[row - 2 * CQ];
        g_bias[row] = bb * scale;
    }
}

// ============ Kernel B: x transpose + hi/lo split -> [b][n][c] fp16 ============
__global__ __launch_bounds__(256) void convx_kernel(const float* __restrict__ x)
{
    __shared__ float sm[64 * 65];
    const int n0 = blockIdx.x * 64, c0 = blockIdx.y * 64, b = blockIdx.z;
    const int t = threadIdx.x;
#pragma unroll
    for (int p = 0; p < 4; p++) {
        int idx = p * 256 + t, c = idx >> 4, l = idx & 15;
        float4 v = *(const float4*)(x + ((size_t)b * CC + c0 + c) * NTOK + n0 + 4 * l);
        sm[c * 65 + 4 * l + 0] = v.x; sm[c * 65 + 4 * l + 1] = v.y;
        sm[c * 65 + 4 * l + 2] = v.z; sm[c * 65 + 4 * l + 3] = v.w;
    }
    __syncthreads();
#pragma unroll
    for (int p = 0; p < 2; p++) {
        int idx = p * 256 + t, n = idx >> 3, cc = idx & 7;
        __align__(16) __half hs[8], ls[8];
#pragma unroll
        for (int i = 0; i < 8; i++) {
            float v = sm[(8 * cc + i) * 65 + n];
            __half h = __float2half_rn(v);
            hs[i] = h;
            ls[i] = __float2half_rn(v - __half2float(h));
        }
        size_t off = ((size_t)b * NTOK + n0 + n) * CC + c0 + 8 * cc;   // FIXED: + c0
        *(uint4*)(g_xh + off) = *(uint4*)hs;
        *(uint4*)(g_xl + off) = *(uint4*)ls;
    }
}

// ============ Kernel C: projections on tensor cores (3-mma hi/lo) ============
#define PXH 0
#define PXL 8448
#define PWH 16896
#define PWL 25344
#define PROJ_WORDS 33792

__global__ __launch_bounds__(256, 1) void projmma_kernel()
{
    extern __shared__ unsigned su[];
    const int t = threadIdx.x, w = t >> 5, lane = t & 31;
    const int quad = lane & 3, qr = lane >> 2;
    const int n0 = blockIdx.x * 64, rg = blockIdx.y, b = blockIdx.z;
    const int r0 = rg * 64;
    const int mr = 16 * (w >> 1), th = 32 * (w & 1);
    const unsigned sbase = (unsigned)__cvta_generic_to_shared(su);

#pragma unroll
    for (int p = 0; p < 8; p++) {
        int idx = p * 256 + t, row = idx >> 5, ch = idx & 31;
        size_t xoff = ((size_t)b * NTOK + n0 + row) * CC + ch * 8;
        size_t woff = (size_t)(r0 + row) * CC + ch * 8;
        cpa16(sbase + (PXH + row * 132 + ch * 4) * 4, g_xh + xoff);
        cpa16(sbase + (PXL + row * 132 + ch * 4) * 4, g_xl + xoff);
        cpa16(sbase + (PWH + row * 132 + ch * 4) * 4, g_wh + woff);
        cpa16(sbase + (PWL + row * 132 + ch * 4) * 4, g_wl + woff);
    }
    asm volatile("cp.async.commit_group;" ::: "memory");
    asm volatile("cp.async.wait_group 0;" ::: "memory");
    __syncthreads();

    const unsigned* XH = su + PXH;
    const unsigned* XL = su + PXL;
    const unsigned* WH = su + PWH;
    const unsigned* WL = su + PWL;

    float4 acc[4];
#pragma unroll
    for (int nt = 0; nt < 4; nt++) acc[nt] = make_float4(0.f, 0.f, 0.f, 0.f);

#pragma unroll
    for (int ks = 0; ks < 16; ks++) {
        unsigned ah[4], al[4];
        int ba = (mr + qr) * 132 + ks * 8 + quad;
        ah[0] = WH[ba];        ah[1] = WH[ba + 8 * 132];
        ah[2] = WH[ba + 4];    ah[3] = WH[ba + 8 * 132 + 4];
        al[0] = WL[ba];        al[1] = WL[ba + 8 * 132];
        al[2] = WL[ba + 4];    al[3] = WL[ba + 8 * 132 + 4];
#pragma unroll
        for (int nt = 0; nt < 4; nt++) {
            int bb = (th + 8 * nt + qr) * 132 + ks * 8 + quad;
            unsigned bh0 = XH[bb], bh1 = XH[bb + 4];
            unsigned bl0 = XL[bb], bl1 = XL[bb + 4];
            mma16(acc[nt], ah, bh0, bh1);
            mma16(acc[nt], al, bh0, bh1);
            mma16(acc[nt], ah, bl0, bl1);
        }
    }
    __syncthreads();

    float* sT = (float*)(su + PXH);   // [64 rows][68]
#pragma unroll
    for (int nt = 0; nt < 4; nt++) {
        int r1 = mr + qr, c = th + 8 * nt + 2 * quad;
        sT[r1 * 68 + c]           = acc[nt].x;
        sT[r1 * 68 + c + 1]       = acc[nt].y;
        sT[(r1 + 8) * 68 + c]     = acc[nt].z;
        sT[(r1 + 8) * 68 + c + 1] = acc[nt].w;
    }
    __syncthreads();

    if (rg == 0) {
        int n = t & 63, rh = t >> 6;
        __align__(16) __half hs[16], ls[16];
#pragma unroll
        for (int i = 0; i < 16; i++) {
            float v = sT[(16 * rh + i) * 68 + n] + g_bias[16 * rh + i];
            __half h = __float2half_rn(v);
            hs[i] = h;
            ls[i] = __float2half_rn(v - __half2float(h));
        }
        size_t tok = (size_t)b * NTOK + n0 + n;
        if (rh < 2) {
            __half* dh = g_qh + tok * CQ + 16 * rh;
            __half* dl = g_ql + tok * CQ + 16 * rh;
            *(uint4*)dh = *(uint4*)hs; *(uint4*)(dh + 8) = ((uint4*)hs)[1];
            *(uint4*)dl = *(uint4*)ls; *(uint4*)(dl + 8) = ((uint4*)ls)[1];
        } else {
            __half* dk = g_kh + tok * CQ + 16 * (rh - 2);
            *(uint4*)dk = *(uint4*)hs; *(uint4*)(dk + 8) = ((uint4*)hs)[1];
        }
    } else {
        int r = t & 63, tc = t >> 6;
        int o = r0 - 64 + r;
        float bias = g_bias[r0 + r];
        __align__(16) __half hs[16];
#pragma unroll
        for (int i = 0; i < 16; i++)
            hs[i] = __float2half_rn(sT[r * 68 + 16 * tc + i] + bias);
        __half* dst = g_vh + ((size_t)b * CC + o) * NTOK + n0 + 16 * tc;
        *(uint4*)dst = *(uint4*)hs; *(uint4*)(dst + 8) = ((uint4*)hs)[1];
    }
}

// ============ Kernel 2: flash attention, 64-key tiles (UNCHANGED from R13) ============
#define OQH  0
#define OQL  1280
#define OP   0
#define OKH0 2560
#define OKH1 3840
#define OV0  5120
#define OV1  14336
#define OAL  23552
#define OSC  23616
#define SMEM_WORDS 23680

__global__ __launch_bounds__(256, 2) void attn_kernel(
    const float* __restrict__ x,
    const float* __restrict__ gamma,
    float* __restrict__ out)
{
    extern __shared__ unsigned su[];
    unsigned* uP = su + OP;
    float* sAl = (float*)(su + OAL);
    float* sSc = (float*)(su + OSC);

    const int t = threadIdx.x, w = t >> 5, lane = t & 31;
    const int quad = lane & 3, qr = lane >> 2;
    const int m_base = 32 * (w >> 2), o_base = 64 * (w & 3);
    const int b = blockIdx.x >> 6, q0 = (blockIdx.x & 63) * 64;
    const unsigned sbase = (unsigned)__cvta_generic_to_shared(su);

    const __half* khp = g_kh + (size_t)b * NTOK * CQ;
    const __half* vb  = g_vh + (size_t)b * CC * NTOK;

    {
        int r = t >> 2, qw = t & 3;
        size_t off = ((size_t)b * NTOK + q0 + r) * CQ + qw * 8;
        *(uint4*)(su + OQH + r * 20 + qw * 4) = *(const uint4*)(g_qh + off);
        *(uint4*)(su + OQL + r * 20 + qw * 4) = *(const uint4*)(g_ql + off);
    }

    const int kr = t >> 2, kc = t & 3;
    const __half* ksrc = khp + (size_t)kr * CQ + kc * 8;
    const unsigned koff = kr * 20 + kc * 4;
    const int vrow = t >> 3, vci = t & 7;
    const __half* vsrc = vb + (size_t)vrow * NTOK + vci * 8;
    const unsigned voff = vrow * 36 + vci * 4;

#pragma unroll
    for (int r = 0; r < 8; r++)
        cpa16(sbase + (OV0 + voff + (32 * r) * 36) * 4, vsrc + (size_t)(32 * r) * NTOK);
    cpa16(sbase + (OKH0 + koff) * 4, ksrc);
    asm volatile("cp.async.commit_group;" ::: "memory");
    asm volatile("cp.async.wait_group 0;" ::: "memory");
    __syncthreads();

    unsigned ah[2][4], alq[2][4];
    if (w < 4) {
        const unsigned* uQh = su + OQH;
        const unsigned* uQl = su + OQL;
#pragma unroll
        for (int ks = 0; ks < 2; ks++) {
            int base = (16 * w + qr) * 20 + ks * 8 + quad;
            ah[ks][0] = uQh[base];      ah[ks][1] = uQh[base + 160];
            ah[ks][2] = uQh[base + 4];  ah[ks][3] = uQh[base + 164];
            alq[ks][0] = uQl[base];     alq[ks][1] = uQl[base + 160];
            alq[ks][2] = uQl[base + 4]; alq[ks][3] = uQl[base + 164];
        }
    }

    float4 acc[2][8];
#pragma unroll
    for (int s = 0; s < 2; s++)
#pragma unroll
        for (int o = 0; o < 8; o++) acc[s][o] = make_float4(0.f, 0.f, 0.f, 0.f);
    float run_m0 = -1e4f, run_m1 = -1e4f, run_l0 = 0.f, run_l1 = 0.f;

    for (int kt = 0; kt < 64; kt++) {
        const int cur = kt & 1;
        const unsigned* uKh = su + (cur ? OKH1 : OKH0);
        const unsigned* uV  = su + (cur ? OV1 : OV0);

        if (kt + 1 < 64) {
            int jn = (kt + 1) * 64;
            unsigned vo = cur ? OV0 : OV1;
            unsigned ko = cur ? OKH0 : OKH1;
#pragma unroll
            for (int r = 0; r < 8; r++)
                cpa16(sbase + (vo + voff + (32 * r) * 36) * 4,
                      vsrc + jn + (size_t)(32 * r) * NTOK);
            cpa16(sbase + (ko + koff) * 4, ksrc + (size_t)jn * CQ);
            asm volatile("cp.async.commit_group;" ::: "memory");
        }

        if (w < 4) {
            float4 sreg[8];
#pragma unroll
            for (int nt = 0; nt < 8; nt++) {
                float4 c = make_float4(0.f, 0.f, 0.f, 0.f);
#pragma unroll
                for (int ks = 0; ks < 2; ks++) {
                    int kb = (nt * 8 + qr) * 20 + ks * 8 + quad;
                    unsigned bh0 = uKh[kb], bh1 = uKh[kb + 4];
                    mma16(c, ah[ks], bh0, bh1);
                    mma16(c, alq[ks], bh0, bh1);
                }
                sreg[nt] = c;
            }
            float mA = -1e30f, mB = -1e30f;
#pragma unroll
            for (int nt = 0; nt < 8; nt++) {
                mA = fmaxf(mA, fmaxf(sreg[nt].x, sreg[nt].y));
                mB = fmaxf(mB, fmaxf(sreg[nt].z, sreg[nt].w));
            }
            mA = fmaxf(mA, __shfl_xor_sync(0xffffffffu, mA, 1));
            mA = fmaxf(mA, __shfl_xor_sync(0xffffffffu, mA, 2));
            mB = fmaxf(mB, __shfl_xor_sync(0xffffffffu, mB, 1));
            mB = fmaxf(mB, __shfl_xor_sync(0xffffffffu, mB, 2));
            float mAn = fmaxf(run_m0, mA), mBn = fmaxf(run_m1, mB);
            float alA = ex2(run_m0 - mAn), alB = ex2(run_m1 - mBn);
            run_m0 = mAn; run_m1 = mBn;
            float sA = 0.f, sB = 0.f;
            int rw = 16 * w + qr;
#pragma unroll
            for (int nt = 0; nt < 8; nt++) {
                float px = ex2(sreg[nt].x - mAn), py = ex2(sreg[nt].y - mAn);
                float pz = ex2(sreg[nt].z - mBn), pw = ex2(sreg[nt].w - mBn);
                sA += px + py; sB += pz + pw;
                __half2 hA = __floats2half2_rn(px, py);
                __half2 hB = __floats2half2_rn(pz, pw);
                uP[rw * 36 + nt * 4 + quad]       = *(unsigned*)&hA;
                uP[(rw + 8) * 36 + nt * 4 + quad] = *(unsigned*)&hB;
            }
            sA += __shfl_xor_sync(0xffffffffu, sA, 1);
            sA += __shfl_xor_sync(0xffffffffu, sA, 2);
            sB += __shfl_xor_sync(0xffffffffu, sB, 1);
            sB += __shfl_xor_sync(0xffffffffu, sB, 2);
            run_l0 = run_l0 * alA + sA;
            run_l1 = run_l1 * alB + sB;
            if (quad == 0) { sAl[rw] = alA; sAl[rw + 8] = alB; }
        }
        __syncthreads();

        float aA0 = sAl[m_base + qr],      aB0 = sAl[m_base + qr + 8];
        float aA1 = sAl[m_base + 16 + qr], aB1 = sAl[m_base + 24 + qr];
#pragma unroll
        for (int o = 0; o < 8; o++) {
            acc[0][o].x *= aA0; acc[0][o].y *= aA0; acc[0][o].z *= aB0; acc[0][o].w *= aB0;
            acc[1][o].x *= aA1; acc[1][o].y *= aA1; acc[1][o].z *= aB1; acc[1][o].w *= aB1;
        }
#pragma unroll
        for (int ks = 0; ks < 4; ks++) {
            unsigned p0[4], p1[4];
            int a0i = (m_base + qr) * 36 + ks * 8 + quad;
            p0[0] = uP[a0i];     p0[1] = uP[a0i + 8 * 36];
            p0[2] = uP[a0i + 4]; p0[3] = uP[a0i + 8 * 36 + 4];
            int a1i = (m_base + 16 + qr) * 36 + ks * 8 + quad;
            p1[0] = uP[a1i];     p1[1] = uP[a1i + 8 * 36];
            p1[2] = uP[a1i + 4]; p1[3] = uP[a1i + 8 * 36 + 4];
#pragma unroll
            for (int ot = 0; ot < 8; ot++) {
                int vi = (o_base + ot * 8 + qr) * 36 + ks * 8 + quad;
                unsigned v0 = uV[vi], v1 = uV[vi + 4];
                mma16(acc[0][ot], p0, v0, v1);
                mma16(acc[1][ot], p1, v0, v1);
            }
        }

        asm volatile("cp.async.wait_group 0;" ::: "memory");
        __syncthreads();
    }

    if (w < 4 && quad == 0) {
        float gm = gamma[0];
        sSc[16 * w + qr]     = gm / run_l0;
        sSc[16 * w + qr + 8] = gm / run_l1;
    }
    __syncthreads();

    const float* xb = x   + (size_t)b * CC * NTOK;
    float*       ob = out + (size_t)b * CC * NTOK;
#pragma unroll
    for (int s = 0; s < 2; s++) {
        int rA = m_base + 16 * s + qr;
        float scA = sSc[rA];
        float scB = sSc[rA + 8];
        int m = q0 + rA;
#pragma unroll
        for (int ot = 0; ot < 8; ot++) {
            int o = o_base + ot * 8 + 2 * quad;
            float4 c = acc[s][ot];
            size_t i00 = (size_t)o * NTOK + m;
            size_t i10 = (size_t)(o + 1) * NTOK + m;
            ob[i00]     = fmaf(scA, c.x, xb[i00]);
            ob[i10]     = fmaf(scA, c.y, xb[i10]);
            ob[i00 + 8] = fmaf(scB, c.z, xb[i00 + 8]);
            ob[i10 + 8] = fmaf(scB, c.w, xb[i10 + 8]);
        }
    }
}

// ============ launch ============
extern "C" void kernel_launch(void* const* d_in, const int* in_sizes, int n_in,
                              void* d_out, int out_size)
{
    const float* x     = (const float*)d_in[0];
    const float* wq    = (const float*)d_in[1];
    const float* bq    = (const float*)d_in[2];
    const float* wk    = (const float*)d_in[3];
    const float* bk    = (const float*)d_in[4];
    const float* wv    = (const float*)d_in[5];
    const float* bv    = (const float*)d_in[6];
    const float* gamma = (const float*)d_in[7];
    float* out = (float*)d_out;

    convw_kernel<<<320, 256>>>(wq, bq, wk, bk, wv, bv);
    convx_kernel<<<dim3(NTOK / 64, CC / 64, BATCH), 256>>>(x);

    const int proj_bytes = PROJ_WORDS * 4;   // 135168
    cudaFuncSetAttribute(projmma_kernel, cudaFuncAttributeMaxDynamicSharedMemorySize, proj_bytes);
    projmma_kernel<<<dim3(NTOK / 64, 5, BATCH), 256, proj_bytes>>>();

    const int smem_bytes = SMEM_WORDS * 4;   // 94720
    cudaFuncSetAttribute(attn_kernel, cudaFuncAttributeMaxDynamicSharedMemorySize, smem_bytes);
    attn_kernel<<<BATCH * (NTOK / 64), 256, smem_bytes>>>(x, gamma, out);
}